// round 14
// baseline (speedup 1.0000x reference)
#include <cuda_runtime.h>
#include <cuda_fp16.h>
#include <math.h>

#define N_NODES 100000
#define N_EDGES 1600000
#define HC 128           // HEADS * OUT_CH
#define IN_CH 64
#define SCAN_CHUNK 512
#define SCAN_BLOCKS ((N_NODES + SCAN_CHUNK - 1) / SCAN_CHUNK)   // 196

// ---------------- scratch (device globals; allocation-free) ----------------
__device__ __half2 g_h[(size_t)N_NODES * 64];    // 25.6 MB fp16 features
__device__ float g_asrc[N_NODES * 4];
__device__ float g_adst[N_NODES * 4];
__device__ int   g_cnt[N_NODES];
__device__ int   g_offs[N_NODES + 1];
__device__ int   g_cursor[N_NODES];
__device__ int   g_part[SCAN_BLOCKS];
__device__ int   g_csr[N_EDGES];

// ---------------- helpers ----------------
__device__ __forceinline__ float lrelu(float v) { return v > 0.f ? v : 0.2f * v; }
__device__ __forceinline__ float4 expl4(float4 a, float4 b) {
    float4 r;
    r.x = __expf(lrelu(a.x + b.x));
    r.y = __expf(lrelu(a.y + b.y));
    r.z = __expf(lrelu(a.z + b.z));
    r.w = __expf(lrelu(a.w + b.w));
    return r;
}
__device__ __forceinline__ float pick4(float4 v, int h) {
    return h == 0 ? v.x : (h == 1 ? v.y : (h == 2 ? v.z : v.w));
}

// ---------------- kernels ----------------
__global__ void k_zero() {
    int i = blockIdx.x * blockDim.x + threadIdx.x;
    if (i < N_NODES) g_cnt[i] = 0;
}

// h = x @ W with 4ch x 4node register blocking (R8 version); fp16 store; fused att halves
__global__ void k_gemm(const float* __restrict__ x, const float* __restrict__ W,
                       const float* __restrict__ att_src, const float* __restrict__ att_dst) {
    __shared__ float Ws[IN_CH * HC];   // [k][ch] 32 KB
    __shared__ float xs[IN_CH * 32];   // [k][n]   8 KB
    const int tid = threadIdx.x;       // 256

    for (int i = tid; i < IN_CH * HC; i += 256) Ws[i] = W[i];

    const int cg = tid & 31;           // channel-quad (ch = cg*4)
    const int ng = tid >> 5;           // node-quad (4 nodes)
    const int head = cg >> 3;
    const float4 As = ((const float4*)att_src)[cg];
    const float4 Ad = ((const float4*)att_dst)[cg];

    for (int tile = blockIdx.x * 32; tile < N_NODES; tile += gridDim.x * 32) {
        __syncthreads();
        {   // stage 32 nodes of x into [k][n] layout
            int n = tid >> 3, kq = tid & 7;
            float4 v0 = ((const float4*)x)[(size_t)(tile + n) * 16 + kq];
            float4 v1 = ((const float4*)x)[(size_t)(tile + n) * 16 + kq + 8];
            xs[(kq * 4 + 0) * 32 + n] = v0.x;
            xs[(kq * 4 + 1) * 32 + n] = v0.y;
            xs[(kq * 4 + 2) * 32 + n] = v0.z;
            xs[(kq * 4 + 3) * 32 + n] = v0.w;
            xs[((kq + 8) * 4 + 0) * 32 + n] = v1.x;
            xs[((kq + 8) * 4 + 1) * 32 + n] = v1.y;
            xs[((kq + 8) * 4 + 2) * 32 + n] = v1.z;
            xs[((kq + 8) * 4 + 3) * 32 + n] = v1.w;
        }
        __syncthreads();

        float4 acc0 = {0,0,0,0}, acc1 = {0,0,0,0}, acc2 = {0,0,0,0}, acc3 = {0,0,0,0};
        #pragma unroll
        for (int k = 0; k < IN_CH; k++) {
            float4 w  = ((const float4*)Ws)[k * 32 + cg];
            float4 xv = ((const float4*)xs)[k * 8 + ng];
            acc0.x += w.x * xv.x; acc0.y += w.y * xv.x; acc0.z += w.z * xv.x; acc0.w += w.w * xv.x;
            acc1.x += w.x * xv.y; acc1.y += w.y * xv.y; acc1.z += w.z * xv.y; acc1.w += w.w * xv.y;
            acc2.x += w.x * xv.z; acc2.y += w.y * xv.z; acc2.z += w.z * xv.z; acc2.w += w.w * xv.z;
            acc3.x += w.x * xv.w; acc3.y += w.y * xv.w; acc3.z += w.z * xv.w; acc3.w += w.w * xv.w;
        }
        const int n0 = tile + ng * 4;
        {
            size_t i0 = (size_t)(n0 + 0) * 64 + cg * 2;
            g_h[i0]     = __floats2half2_rn(acc0.x, acc0.y);
            g_h[i0 + 1] = __floats2half2_rn(acc0.z, acc0.w);
            size_t i1 = (size_t)(n0 + 1) * 64 + cg * 2;
            g_h[i1]     = __floats2half2_rn(acc1.x, acc1.y);
            g_h[i1 + 1] = __floats2half2_rn(acc1.z, acc1.w);
            size_t i2 = (size_t)(n0 + 2) * 64 + cg * 2;
            g_h[i2]     = __floats2half2_rn(acc2.x, acc2.y);
            g_h[i2 + 1] = __floats2half2_rn(acc2.z, acc2.w);
            size_t i3 = (size_t)(n0 + 3) * 64 + cg * 2;
            g_h[i3]     = __floats2half2_rn(acc3.x, acc3.y);
            g_h[i3 + 1] = __floats2half2_rn(acc3.z, acc3.w);
        }

        // attention halves: reduce 8 lanes (one head) per node
        float ps[4], pd[4];
        ps[0] = acc0.x*As.x + acc0.y*As.y + acc0.z*As.z + acc0.w*As.w;
        ps[1] = acc1.x*As.x + acc1.y*As.y + acc1.z*As.z + acc1.w*As.w;
        ps[2] = acc2.x*As.x + acc2.y*As.y + acc2.z*As.z + acc2.w*As.w;
        ps[3] = acc3.x*As.x + acc3.y*As.y + acc3.z*As.z + acc3.w*As.w;
        pd[0] = acc0.x*Ad.x + acc0.y*Ad.y + acc0.z*Ad.z + acc0.w*Ad.w;
        pd[1] = acc1.x*Ad.x + acc1.y*Ad.y + acc1.z*Ad.z + acc1.w*Ad.w;
        pd[2] = acc2.x*Ad.x + acc2.y*Ad.y + acc2.z*Ad.z + acc2.w*Ad.w;
        pd[3] = acc3.x*Ad.x + acc3.y*Ad.y + acc3.z*Ad.z + acc3.w*Ad.w;
        #pragma unroll
        for (int o = 1; o < 8; o <<= 1) {
            #pragma unroll
            for (int j = 0; j < 4; j++) {
                ps[j] += __shfl_xor_sync(0xffffffffu, ps[j], o);
                pd[j] += __shfl_xor_sync(0xffffffffu, pd[j], o);
            }
        }
        if ((cg & 7) == 0) {
            #pragma unroll
            for (int j = 0; j < 4; j++) {
                g_asrc[(n0 + j) * 4 + head] = ps[j];
                g_adst[(n0 + j) * 4 + head] = pd[j];
            }
        }
    }
}

__global__ void k_hist(const int* __restrict__ ei) {
    int i = blockIdx.x * blockDim.x + threadIdx.x;
    if (i < N_EDGES) atomicAdd(&g_cnt[ei[N_EDGES + i]], 1);
}

__global__ void k_scan1() {
    __shared__ int sm[SCAN_CHUNK];
    int b = blockIdx.x, t = threadIdx.x;
    int i = b * SCAN_CHUNK + t;
    int v = (i < N_NODES) ? g_cnt[i] : 0;
    sm[t] = v;
    __syncthreads();
    #pragma unroll
    for (int o = 1; o < SCAN_CHUNK; o <<= 1) {
        int add = (t >= o) ? sm[t - o] : 0;
        __syncthreads();
        sm[t] += add;
        __syncthreads();
    }
    if (i < N_NODES) g_offs[i] = sm[t] - v;
    if (t == SCAN_CHUNK - 1) g_part[b] = sm[t];
}

__global__ void k_scan2() {
    __shared__ int sm[256];
    int t = threadIdx.x;
    int v = (t < SCAN_BLOCKS) ? g_part[t] : 0;
    sm[t] = v;
    __syncthreads();
    #pragma unroll
    for (int o = 1; o < 256; o <<= 1) {
        int add = (t >= o) ? sm[t - o] : 0;
        __syncthreads();
        sm[t] += add;
        __syncthreads();
    }
    if (t < SCAN_BLOCKS) g_part[t] = sm[t] - v;
}

__global__ void k_scan3() {
    int i = blockIdx.x * blockDim.x + threadIdx.x;
    if (i < N_NODES) {
        int off = g_offs[i] + g_part[i / SCAN_CHUNK];
        g_offs[i] = off;
        g_cursor[i] = off;
    }
    if (i == 0) g_offs[N_NODES] = N_EDGES;
}

__global__ void k_scatter(const int* __restrict__ ei) {
    int i = blockIdx.x * blockDim.x + threadIdx.x;
    if (i >= N_EDGES) return;
    int d = ei[N_EDGES + i];
    int pos = atomicAdd(&g_cursor[d], 1);
    g_csr[pos] = ei[i];
}

// one warp per dst, SINGLE pass over edges: accumulate unnormalized weighted
// sum AND denominator together; normalize once at the end.
//   out = (sum_e ex_e * h[src_e] + ex_self * h[d]) / den
__global__ void k_fused(const float* __restrict__ bias, float* __restrict__ out) {
    int d    = (blockIdx.x * blockDim.x + threadIdx.x) >> 5;
    int lane = threadIdx.x & 31;
    if (d >= N_NODES) return;
    const int head = lane >> 3;
    const int beg = g_offs[d], end = g_offs[d + 1];

    const float4 ad4  = ((const float4*)g_adst)[d];
    const float4 as_d = ((const float4*)g_asrc)[d];

    float4 den = {0,0,0,0};   // lane-partial denominator
    float4 acc = {0,0,0,0};   // unnormalized weighted features (my 4 channels)

    for (int base = beg; base < end; base += 32) {
        int e = base + lane;
        int s_my = 0;
        float4 ex4 = {0,0,0,0};
        if (e < end) {
            s_my = g_csr[e];
            float4 as = ((const float4*)g_asrc)[s_my];
            ex4 = expl4(as, ad4);
            den.x += ex4.x; den.y += ex4.y; den.z += ex4.z; den.w += ex4.w;
        }
        int n = min(32, end - base);
        for (int k = 0; k < n; k++) {
            int s = __shfl_sync(0xffffffffu, s_my, k);
            float e0 = __shfl_sync(0xffffffffu, ex4.x, k);
            float e1 = __shfl_sync(0xffffffffu, ex4.y, k);
            float e2 = __shfl_sync(0xffffffffu, ex4.z, k);
            float e3 = __shfl_sync(0xffffffffu, ex4.w, k);
            float w = head == 0 ? e0 : (head == 1 ? e1 : (head == 2 ? e2 : e3));
            float2 raw = ((const float2*)g_h)[(size_t)s * 32 + lane];
            float2 f01 = __half22float2(*(__half2*)&raw.x);
            float2 f23 = __half22float2(*(__half2*)&raw.y);
            acc.x += f01.x * w; acc.y += f01.y * w;
            acc.z += f23.x * w; acc.w += f23.y * w;
        }
    }

    // reduce denominator across warp, add self loop
    #pragma unroll
    for (int o = 16; o > 0; o >>= 1) {
        den.x += __shfl_xor_sync(0xffffffffu, den.x, o);
        den.y += __shfl_xor_sync(0xffffffffu, den.y, o);
        den.z += __shfl_xor_sync(0xffffffffu, den.z, o);
        den.w += __shfl_xor_sync(0xffffffffu, den.w, o);
    }
    float4 eself = expl4(as_d, ad4);
    den.x += eself.x; den.y += eself.y; den.z += eself.z; den.w += eself.w;

    // self-loop contribution (unnormalized)
    {
        float es = pick4(eself, head);
        float2 raw = ((const float2*)g_h)[(size_t)d * 32 + lane];
        float2 f01 = __half22float2(*(__half2*)&raw.x);
        float2 f23 = __half22float2(*(__half2*)&raw.y);
        acc.x += f01.x * es; acc.y += f01.y * es;
        acc.z += f23.x * es; acc.w += f23.y * es;
    }

    // normalize once
    float inv_my = 1.f / (pick4(den, head) + 1e-16f);
    acc.x *= inv_my; acc.y *= inv_my; acc.z *= inv_my; acc.w *= inv_my;

    // bias + log_softmax over 128 channels
    float4 b = ((const float4*)bias)[lane];
    acc.x += b.x; acc.y += b.y; acc.z += b.z; acc.w += b.w;
    float mx = fmaxf(fmaxf(acc.x, acc.y), fmaxf(acc.z, acc.w));
    #pragma unroll
    for (int o = 16; o > 0; o >>= 1) mx = fmaxf(mx, __shfl_xor_sync(0xffffffffu, mx, o));
    float sm = __expf(acc.x - mx) + __expf(acc.y - mx) + __expf(acc.z - mx) + __expf(acc.w - mx);
    #pragma unroll
    for (int o = 16; o > 0; o >>= 1) sm += __shfl_xor_sync(0xffffffffu, sm, o);
    float lse = mx + __logf(sm);
    float4 r = make_float4(acc.x - lse, acc.y - lse, acc.z - lse, acc.w - lse);
    ((float4*)out)[(size_t)d * 32 + lane] = r;
}

// ---------------- launch ----------------
extern "C" void kernel_launch(void* const* d_in, const int* in_sizes, int n_in,
                              void* d_out, int out_size) {
    const float* x       = (const float*)d_in[0];
    const int*   ei      = (const int*)d_in[1];
    const float* W       = (const float*)d_in[2];
    const float* att_src = (const float*)d_in[3];
    const float* att_dst = (const float*)d_in[4];
    const float* bias    = (const float*)d_in[5];
    float* out = (float*)d_out;

    k_zero<<<(N_NODES + 255) / 256, 256>>>();
    k_gemm<<<1184, 256>>>(x, W, att_src, att_dst);
    k_hist<<<(N_EDGES + 255) / 256, 256>>>(ei);
    k_scan1<<<SCAN_BLOCKS, SCAN_CHUNK>>>();
    k_scan2<<<1, 256>>>();
    k_scan3<<<(N_NODES + 255) / 256, 256>>>();
    k_scatter<<<(N_EDGES + 255) / 256, 256>>>(ei);
    k_fused<<<(N_NODES * 32 + 255) / 256, 256>>>(bias, out);
}

// round 16
// speedup vs baseline: 1.7554x; 1.7554x over previous
#include <cuda_runtime.h>
#include <cuda_fp16.h>
#include <math.h>

#define N_NODES 100000
#define N_EDGES 1600000
#define HC 128           // HEADS * OUT_CH
#define IN_CH 64
#define SCAN_CHUNK 512
#define SCAN_BLOCKS ((N_NODES + SCAN_CHUNK - 1) / SCAN_CHUNK)   // 196

// ---------------- scratch (device globals; allocation-free) ----------------
__device__ __half2 g_h[(size_t)N_NODES * 64];    // 25.6 MB fp16 features
__device__ float g_asrc[N_NODES * 4];
__device__ float g_adst[N_NODES * 4];
__device__ int   g_cnt[N_NODES];
__device__ int   g_offs[N_NODES + 1];
__device__ int   g_cursor[N_NODES];
__device__ int   g_part[SCAN_BLOCKS];
__device__ int   g_csr[N_EDGES];

// ---------------- helpers ----------------
__device__ __forceinline__ float lrelu(float v) { return v > 0.f ? v : 0.2f * v; }
__device__ __forceinline__ float4 expl4(float4 a, float4 b) {
    float4 r;
    r.x = __expf(lrelu(a.x + b.x));
    r.y = __expf(lrelu(a.y + b.y));
    r.z = __expf(lrelu(a.z + b.z));
    r.w = __expf(lrelu(a.w + b.w));
    return r;
}
__device__ __forceinline__ float pick4(float4 v, int h) {
    return h == 0 ? v.x : (h == 1 ? v.y : (h == 2 ? v.z : v.w));
}

// ---------------- kernels ----------------
__global__ void k_zero() {
    int i = blockIdx.x * blockDim.x + threadIdx.x;
    if (i < N_NODES) g_cnt[i] = 0;
}

// h = x @ W with 4ch x 4node register blocking (R8 version); fp16 store; fused att halves
__global__ void k_gemm(const float* __restrict__ x, const float* __restrict__ W,
                       const float* __restrict__ att_src, const float* __restrict__ att_dst) {
    __shared__ float Ws[IN_CH * HC];   // [k][ch] 32 KB
    __shared__ float xs[IN_CH * 32];   // [k][n]   8 KB
    const int tid = threadIdx.x;       // 256

    for (int i = tid; i < IN_CH * HC; i += 256) Ws[i] = W[i];

    const int cg = tid & 31;           // channel-quad (ch = cg*4)
    const int ng = tid >> 5;           // node-quad (4 nodes)
    const int head = cg >> 3;
    const float4 As = ((const float4*)att_src)[cg];
    const float4 Ad = ((const float4*)att_dst)[cg];

    for (int tile = blockIdx.x * 32; tile < N_NODES; tile += gridDim.x * 32) {
        __syncthreads();
        {   // stage 32 nodes of x into [k][n] layout
            int n = tid >> 3, kq = tid & 7;
            float4 v0 = ((const float4*)x)[(size_t)(tile + n) * 16 + kq];
            float4 v1 = ((const float4*)x)[(size_t)(tile + n) * 16 + kq + 8];
            xs[(kq * 4 + 0) * 32 + n] = v0.x;
            xs[(kq * 4 + 1) * 32 + n] = v0.y;
            xs[(kq * 4 + 2) * 32 + n] = v0.z;
            xs[(kq * 4 + 3) * 32 + n] = v0.w;
            xs[((kq + 8) * 4 + 0) * 32 + n] = v1.x;
            xs[((kq + 8) * 4 + 1) * 32 + n] = v1.y;
            xs[((kq + 8) * 4 + 2) * 32 + n] = v1.z;
            xs[((kq + 8) * 4 + 3) * 32 + n] = v1.w;
        }
        __syncthreads();

        float4 acc0 = {0,0,0,0}, acc1 = {0,0,0,0}, acc2 = {0,0,0,0}, acc3 = {0,0,0,0};
        #pragma unroll
        for (int k = 0; k < IN_CH; k++) {
            float4 w  = ((const float4*)Ws)[k * 32 + cg];
            float4 xv = ((const float4*)xs)[k * 8 + ng];
            acc0.x += w.x * xv.x; acc0.y += w.y * xv.x; acc0.z += w.z * xv.x; acc0.w += w.w * xv.x;
            acc1.x += w.x * xv.y; acc1.y += w.y * xv.y; acc1.z += w.z * xv.y; acc1.w += w.w * xv.y;
            acc2.x += w.x * xv.z; acc2.y += w.y * xv.z; acc2.z += w.z * xv.z; acc2.w += w.w * xv.z;
            acc3.x += w.x * xv.w; acc3.y += w.y * xv.w; acc3.z += w.z * xv.w; acc3.w += w.w * xv.w;
        }
        const int n0 = tile + ng * 4;
        {
            size_t i0 = (size_t)(n0 + 0) * 64 + cg * 2;
            g_h[i0]     = __floats2half2_rn(acc0.x, acc0.y);
            g_h[i0 + 1] = __floats2half2_rn(acc0.z, acc0.w);
            size_t i1 = (size_t)(n0 + 1) * 64 + cg * 2;
            g_h[i1]     = __floats2half2_rn(acc1.x, acc1.y);
            g_h[i1 + 1] = __floats2half2_rn(acc1.z, acc1.w);
            size_t i2 = (size_t)(n0 + 2) * 64 + cg * 2;
            g_h[i2]     = __floats2half2_rn(acc2.x, acc2.y);
            g_h[i2 + 1] = __floats2half2_rn(acc2.z, acc2.w);
            size_t i3 = (size_t)(n0 + 3) * 64 + cg * 2;
            g_h[i3]     = __floats2half2_rn(acc3.x, acc3.y);
            g_h[i3 + 1] = __floats2half2_rn(acc3.z, acc3.w);
        }

        // attention halves: reduce 8 lanes (one head) per node
        float ps[4], pd[4];
        ps[0] = acc0.x*As.x + acc0.y*As.y + acc0.z*As.z + acc0.w*As.w;
        ps[1] = acc1.x*As.x + acc1.y*As.y + acc1.z*As.z + acc1.w*As.w;
        ps[2] = acc2.x*As.x + acc2.y*As.y + acc2.z*As.z + acc2.w*As.w;
        ps[3] = acc3.x*As.x + acc3.y*As.y + acc3.z*As.z + acc3.w*As.w;
        pd[0] = acc0.x*Ad.x + acc0.y*Ad.y + acc0.z*Ad.z + acc0.w*Ad.w;
        pd[1] = acc1.x*Ad.x + acc1.y*Ad.y + acc1.z*Ad.z + acc1.w*Ad.w;
        pd[2] = acc2.x*Ad.x + acc2.y*Ad.y + acc2.z*Ad.z + acc2.w*Ad.w;
        pd[3] = acc3.x*Ad.x + acc3.y*Ad.y + acc3.z*Ad.z + acc3.w*Ad.w;
        #pragma unroll
        for (int o = 1; o < 8; o <<= 1) {
            #pragma unroll
            for (int j = 0; j < 4; j++) {
                ps[j] += __shfl_xor_sync(0xffffffffu, ps[j], o);
                pd[j] += __shfl_xor_sync(0xffffffffu, pd[j], o);
            }
        }
        if ((cg & 7) == 0) {
            #pragma unroll
            for (int j = 0; j < 4; j++) {
                g_asrc[(n0 + j) * 4 + head] = ps[j];
                g_adst[(n0 + j) * 4 + head] = pd[j];
            }
        }
    }
}

__global__ void k_hist(const int* __restrict__ ei) {
    int i = blockIdx.x * blockDim.x + threadIdx.x;
    if (i < N_EDGES) atomicAdd(&g_cnt[ei[N_EDGES + i]], 1);
}

__global__ void k_scan1() {
    __shared__ int sm[SCAN_CHUNK];
    int b = blockIdx.x, t = threadIdx.x;
    int i = b * SCAN_CHUNK + t;
    int v = (i < N_NODES) ? g_cnt[i] : 0;
    sm[t] = v;
    __syncthreads();
    #pragma unroll
    for (int o = 1; o < SCAN_CHUNK; o <<= 1) {
        int add = (t >= o) ? sm[t - o] : 0;
        __syncthreads();
        sm[t] += add;
        __syncthreads();
    }
    if (i < N_NODES) g_offs[i] = sm[t] - v;
    if (t == SCAN_CHUNK - 1) g_part[b] = sm[t];
}

__global__ void k_scan2() {
    __shared__ int sm[256];
    int t = threadIdx.x;
    int v = (t < SCAN_BLOCKS) ? g_part[t] : 0;
    sm[t] = v;
    __syncthreads();
    #pragma unroll
    for (int o = 1; o < 256; o <<= 1) {
        int add = (t >= o) ? sm[t - o] : 0;
        __syncthreads();
        sm[t] += add;
        __syncthreads();
    }
    if (t < SCAN_BLOCKS) g_part[t] = sm[t] - v;
}

__global__ void k_scan3() {
    int i = blockIdx.x * blockDim.x + threadIdx.x;
    if (i < N_NODES) {
        int off = g_offs[i] + g_part[i / SCAN_CHUNK];
        g_offs[i] = off;
        g_cursor[i] = off;
    }
    if (i == 0) g_offs[N_NODES] = N_EDGES;
}

__global__ void k_scatter(const int* __restrict__ ei) {
    int i = blockIdx.x * blockDim.x + threadIdx.x;
    if (i >= N_EDGES) return;
    int d = ei[N_EDGES + i];
    int pos = atomicAdd(&g_cursor[d], 1);
    g_csr[pos] = ei[i];
}

// one warp per dst: two-pass (pass 1 = denom + L1 prefetch; pass 2 = gather)
// R8 structure; pass-2 inner loop pipelined 2 edges deep for MLP.
__global__ void k_fused(const float* __restrict__ bias, float* __restrict__ out) {
    int d    = (blockIdx.x * blockDim.x + threadIdx.x) >> 5;
    int lane = threadIdx.x & 31;
    if (d >= N_NODES) return;
    const int head = lane >> 3;
    const int beg = g_offs[d], end = g_offs[d + 1];

    const float4 ad4  = ((const float4*)g_adst)[d];
    const float4 as_d = ((const float4*)g_asrc)[d];

    // pass 1: denominator (also warms L1 with csr + asrc lines for pass 2)
    float4 den = {0,0,0,0};
    for (int e = beg + lane; e < end; e += 32) {
        float4 as = ((const float4*)g_asrc)[g_csr[e]];
        float4 ex = expl4(as, ad4);
        den.x += ex.x; den.y += ex.y; den.z += ex.z; den.w += ex.w;
    }
    #pragma unroll
    for (int o = 16; o > 0; o >>= 1) {
        den.x += __shfl_xor_sync(0xffffffffu, den.x, o);
        den.y += __shfl_xor_sync(0xffffffffu, den.y, o);
        den.z += __shfl_xor_sync(0xffffffffu, den.z, o);
        den.w += __shfl_xor_sync(0xffffffffu, den.w, o);
    }
    float4 eself = expl4(as_d, ad4);
    den.x += eself.x; den.y += eself.y; den.z += eself.z; den.w += eself.w;
    float4 inv4;
    inv4.x = 1.f / (den.x + 1e-16f);
    inv4.y = 1.f / (den.y + 1e-16f);
    inv4.z = 1.f / (den.z + 1e-16f);
    inv4.w = 1.f / (den.w + 1e-16f);

    // self-loop contribution
    float al_self = pick4(eself, head) * pick4(inv4, head);
    float4 acc;
    {
        float2 raw = ((const float2*)g_h)[(size_t)d * 32 + lane];
        float2 f01 = __half22float2(*(__half2*)&raw.x);
        float2 f23 = __half22float2(*(__half2*)&raw.y);
        acc.x = f01.x * al_self; acc.y = f01.y * al_self;
        acc.z = f23.x * al_self; acc.w = f23.y * al_self;
    }

    // pass 2: edge contributions, 32-edge chunks, 2 edges in flight
    for (int base = beg; base < end; base += 32) {
        int e = base + lane;
        int s_my = 0;
        float4 al4 = {0,0,0,0};
        if (e < end) {
            s_my = g_csr[e];
            float4 as = ((const float4*)g_asrc)[s_my];
            float4 ex = expl4(as, ad4);
            al4.x = ex.x * inv4.x; al4.y = ex.y * inv4.y;
            al4.z = ex.z * inv4.z; al4.w = ex.w * inv4.w;
        }
        int n = min(32, end - base);
        int k = 0;
        for (; k + 1 < n; k += 2) {
            // broadcast both edges' src + alphas first, then issue both loads
            int sA = __shfl_sync(0xffffffffu, s_my, k);
            int sB = __shfl_sync(0xffffffffu, s_my, k + 1);
            float a0A = __shfl_sync(0xffffffffu, al4.x, k);
            float a1A = __shfl_sync(0xffffffffu, al4.y, k);
            float a2A = __shfl_sync(0xffffffffu, al4.z, k);
            float a3A = __shfl_sync(0xffffffffu, al4.w, k);
            float a0B = __shfl_sync(0xffffffffu, al4.x, k + 1);
            float a1B = __shfl_sync(0xffffffffu, al4.y, k + 1);
            float a2B = __shfl_sync(0xffffffffu, al4.z, k + 1);
            float a3B = __shfl_sync(0xffffffffu, al4.w, k + 1);
            float2 rawA = ((const float2*)g_h)[(size_t)sA * 32 + lane];
            float2 rawB = ((const float2*)g_h)[(size_t)sB * 32 + lane];
            float alA = head == 0 ? a0A : (head == 1 ? a1A : (head == 2 ? a2A : a3A));
            float alB = head == 0 ? a0B : (head == 1 ? a1B : (head == 2 ? a2B : a3B));
            float2 fA01 = __half22float2(*(__half2*)&rawA.x);
            float2 fA23 = __half22float2(*(__half2*)&rawA.y);
            acc.x += fA01.x * alA; acc.y += fA01.y * alA;
            acc.z += fA23.x * alA; acc.w += fA23.y * alA;
            float2 fB01 = __half22float2(*(__half2*)&rawB.x);
            float2 fB23 = __half22float2(*(__half2*)&rawB.y);
            acc.x += fB01.x * alB; acc.y += fB01.y * alB;
            acc.z += fB23.x * alB; acc.w += fB23.y * alB;
        }
        if (k < n) {
            int s = __shfl_sync(0xffffffffu, s_my, k);
            float a0 = __shfl_sync(0xffffffffu, al4.x, k);
            float a1 = __shfl_sync(0xffffffffu, al4.y, k);
            float a2 = __shfl_sync(0xffffffffu, al4.z, k);
            float a3 = __shfl_sync(0xffffffffu, al4.w, k);
            float al = head == 0 ? a0 : (head == 1 ? a1 : (head == 2 ? a2 : a3));
            float2 raw = ((const float2*)g_h)[(size_t)s * 32 + lane];
            float2 f01 = __half22float2(*(__half2*)&raw.x);
            float2 f23 = __half22float2(*(__half2*)&raw.y);
            acc.x += f01.x * al; acc.y += f01.y * al;
            acc.z += f23.x * al; acc.w += f23.y * al;
        }
    }

    // bias + log_softmax over 128 channels
    float4 b = ((const float4*)bias)[lane];
    acc.x += b.x; acc.y += b.y; acc.z += b.z; acc.w += b.w;
    float mx = fmaxf(fmaxf(acc.x, acc.y), fmaxf(acc.z, acc.w));
    #pragma unroll
    for (int o = 16; o > 0; o >>= 1) mx = fmaxf(mx, __shfl_xor_sync(0xffffffffu, mx, o));
    float sm = __expf(acc.x - mx) + __expf(acc.y - mx) + __expf(acc.z - mx) + __expf(acc.w - mx);
    #pragma unroll
    for (int o = 16; o > 0; o >>= 1) sm += __shfl_xor_sync(0xffffffffu, sm, o);
    float lse = mx + __logf(sm);
    float4 r = make_float4(acc.x - lse, acc.y - lse, acc.z - lse, acc.w - lse);
    ((float4*)out)[(size_t)d * 32 + lane] = r;
}

// ---------------- launch ----------------
extern "C" void kernel_launch(void* const* d_in, const int* in_sizes, int n_in,
                              void* d_out, int out_size) {
    const float* x       = (const float*)d_in[0];
    const int*   ei      = (const int*)d_in[1];
    const float* W       = (const float*)d_in[2];
    const float* att_src = (const float*)d_in[3];
    const float* att_dst = (const float*)d_in[4];
    const float* bias    = (const float*)d_in[5];
    float* out = (float*)d_out;

    k_zero<<<(N_NODES + 255) / 256, 256>>>();
    k_gemm<<<1184, 256>>>(x, W, att_src, att_dst);
    k_hist<<<(N_EDGES + 255) / 256, 256>>>(ei);
    k_scan1<<<SCAN_BLOCKS, SCAN_CHUNK>>>();
    k_scan2<<<1, 256>>>();
    k_scan3<<<(N_NODES + 255) / 256, 256>>>();
    k_scatter<<<(N_EDGES + 255) / 256, 256>>>(ei);
    k_fused<<<(N_NODES * 32 + 255) / 256, 256>>>(bias, out);
}